// round 10
// baseline (speedup 1.0000x reference)
#include <cuda_runtime.h>
#include <cuda_fp16.h>
#include <float.h>
#include <math.h>
#include <cstdint>

#define N_NODES 131072
#define B_SEG   1024
#define H_DIM   128
#define TILE_N  128
#define NTILES  (N_NODES / TILE_N)
#define NSTAGES 3

// Tiles: [128 rows][136 halves] -> 272 B row stride (16B-aligned, 17x16B units)
#define A_STRIDE 136
#define B_STRIDE 136

__device__ float g_v[N_NODES];
__device__ int   g_off[B_SEG + 1];

// ---- k_node smem layout (bytes) ----
static constexpr int STAGE   = 34816;                   // Ah per stage
static constexpr int SM_B    = NSTAGES * STAGE;         // 104448
static constexpr int SM_FLT  = SM_B + 34816;            // 139264
// floats: lins[3][128], ps[512], b1s[128], w2s[128] = 1152 floats
static constexpr int SMEM_K1 = SM_FLT + 1152 * 4;       // 143872

// ---------------------------------------------------------------------------
__device__ __forceinline__ uint32_t smem_u32(const void* p) {
    uint32_t a;
    asm("{ .reg .u64 t; cvta.to.shared.u64 t, %1; cvt.u32.u64 %0, t; }"
        : "=r"(a) : "l"(p));
    return a;
}
__device__ __forceinline__ void bar_sync(int id, int cnt) {
    asm volatile("bar.sync %0, %1;" :: "r"(id), "r"(cnt) : "memory");
}
__device__ __forceinline__ void bar_arrive(int id, int cnt) {
    asm volatile("bar.arrive %0, %1;" :: "r"(id), "r"(cnt) : "memory");
}
__device__ __forceinline__ void ldsm_x4(uint32_t* r, uint32_t a) {
    asm volatile("ldmatrix.sync.aligned.m8n8.x4.shared.b16 {%0,%1,%2,%3}, [%4];"
                 : "=r"(r[0]), "=r"(r[1]), "=r"(r[2]), "=r"(r[3]) : "r"(a));
}
__device__ __forceinline__ void ldsm_x2t(uint32_t* r, uint32_t a) {
    asm volatile("ldmatrix.sync.aligned.m8n8.x2.trans.shared.b16 {%0,%1}, [%2];"
                 : "=r"(r[0]), "=r"(r[1]) : "r"(a));
}
__device__ __forceinline__ void mma16816(float* d, const uint32_t* a, const uint32_t* b) {
    asm volatile(
        "mma.sync.aligned.m16n8k16.row.col.f32.f16.f16.f32 "
        "{%0,%1,%2,%3}, {%4,%5,%6,%7}, {%8,%9}, {%0,%1,%2,%3};"
        : "+f"(d[0]), "+f"(d[1]), "+f"(d[2]), "+f"(d[3])
        : "r"(a[0]), "r"(a[1]), "r"(a[2]), "r"(a[3]), "r"(b[0]), "r"(b[1]));
}

// producer helpers: paired-c layout (lane owns c = 2*lane, 2*lane+1 per half)
__device__ __forceinline__ void load2(const float4* __restrict__ emb4, size_t ng,
                                      int lane, float4 x[2][4]) {
    #pragma unroll
    for (int k = 0; k < 2; ++k) {
        const float4* p = emb4 + (ng + k) * 128;
        x[k][0] = p[2 * lane];
        x[k][1] = p[2 * lane + 1];
        x[k][2] = p[64 + 2 * lane];
        x[k][3] = p[64 + 2 * lane + 1];
    }
}

__device__ __forceinline__ void proc2(const float4 x[2][4], char* AhS, float* linsS,
                                      int nl, int lane, const float wlr[3][4]) {
    #pragma unroll
    for (int k = 0; k < 2; ++k) {
        float l = 0.f;
        #pragma unroll
        for (int r = 0; r < 3; ++r) {
            const float* xr0 = (r == 0) ? &x[k][0].x : (r == 1) ? &x[k][0].y : &x[k][0].z;
            // unrolled by component below instead (avoid pointer trick):
        }
        l = fmaf(x[k][0].x, wlr[0][0], l);
        l = fmaf(x[k][1].x, wlr[0][1], l);
        l = fmaf(x[k][2].x, wlr[0][2], l);
        l = fmaf(x[k][3].x, wlr[0][3], l);
        l = fmaf(x[k][0].y, wlr[1][0], l);
        l = fmaf(x[k][1].y, wlr[1][1], l);
        l = fmaf(x[k][2].y, wlr[1][2], l);
        l = fmaf(x[k][3].y, wlr[1][3], l);
        l = fmaf(x[k][0].z, wlr[2][0], l);
        l = fmaf(x[k][1].z, wlr[2][1], l);
        l = fmaf(x[k][2].z, wlr[2][2], l);
        l = fmaf(x[k][3].z, wlr[2][3], l);

        __half2 h01 = __floats2half2_rn(x[k][0].w, x[k][1].w);
        __half2 h23 = __floats2half2_rn(x[k][2].w, x[k][3].w);
        int row = (nl + k) * A_STRIDE;
        *(__half2*)(AhS + (row + 2 * lane) * 2)      = h01;
        *(__half2*)(AhS + (row + 64 + 2 * lane) * 2) = h23;

        #pragma unroll
        for (int d = 16; d > 0; d >>= 1)
            l += __shfl_xor_sync(0xffffffffu, l, d);
        if (lane == 0) linsS[nl + k] = l;
    }
}

// ---------------------------------------------------------------------------
// Kernel 1: persistent warp-specialized node readout (fp16 single-term MMA)
// ---------------------------------------------------------------------------
__global__ __launch_bounds__(512, 1)
void k_node(const float4* __restrict__ emb4,
            const int*    __restrict__ batch,
            const float*  __restrict__ W_lins,
            const float*  __restrict__ b_lins,
            const float*  __restrict__ W1,
            const float*  __restrict__ b1,
            const float*  __restrict__ W2,
            const float*  __restrict__ b2)
{
    extern __shared__ __align__(16) char smem[];
    char*  Bh   = smem + SM_B;
    float* lins = (float*)(smem + SM_FLT);   // [3][128]
    float* ps   = lins + NSTAGES * 128;      // [128][4]
    float* b1s  = ps + 512;                  // [128]
    float* w2s  = b1s + 128;                 // [128]

    const int tid  = threadIdx.x;
    const int lane = tid & 31;
    const int wid  = tid >> 5;
    const bool producer = (wid < 8);
    const uint32_t sbase = smem_u32(smem);

    // ---- prelude: segment-offset scatter (batch sorted) ----
    for (int i = blockIdx.x * 512 + tid; i < N_NODES; i += gridDim.x * 512) {
        int b    = batch[i];
        int prev = (i == 0) ? -1 : batch[i - 1];
        for (int bb = prev + 1; bb <= b; ++bb) g_off[bb] = i;
        if (i == N_NODES - 1)
            for (int bb = b + 1; bb <= B_SEG; ++bb) g_off[bb] = N_NODES;
    }

    // one-time staging: W1 -> fp16 B tile, b1s, w2s
    for (int i = tid; i < 128 * 128 / 4; i += 512) {
        float4 w = ((const float4*)W1)[i];
        int c  = i >> 5;
        int h4 = (i & 31) * 4;
        int off = (c * B_STRIDE + h4) * 2;
        *(__half2*)(Bh + off)     = __floats2half2_rn(w.x, w.y);
        *(__half2*)(Bh + off + 4) = __floats2half2_rn(w.z, w.w);
    }
    if (tid < 128) { b1s[tid] = b1[tid]; w2s[tid] = W2[tid]; }

    // producers: W_lins at paired-c positions
    float wlr[3][4];
    if (producer) {
        #pragma unroll
        for (int r = 0; r < 3; ++r) {
            wlr[r][0] = W_lins[r * 128 + 2 * lane];
            wlr[r][1] = W_lins[r * 128 + 2 * lane + 1];
            wlr[r][2] = W_lins[r * 128 + 64 + 2 * lane];
            wlr[r][3] = W_lins[r * 128 + 64 + 2 * lane + 1];
        }
    }
    const float cst = b_lins[0] + b_lins[1] + b_lins[2] + b2[0];
    __syncthreads();

    int it = 0;
    for (int t = blockIdx.x; t < NTILES; t += gridDim.x, ++it) {
        const int s  = it % NSTAGES;
        const int n0 = t * TILE_N;

        if (producer) {
            if (it >= NSTAGES) bar_sync(5 + s, 512);     // wait stage empty
            char*  AhS   = smem + s * STAGE;
            float* linsS = lins + s * 128;
            const int nbase = wid * 16;
            const size_t gbase = (size_t)(n0 + nbase);

            // software-pipelined 2-node chunks (8 chunks), reg double-buffer
            float4 xa[2][4], xb[2][4];
            load2(emb4, gbase, lane, xa);
            #pragma unroll
            for (int ch = 0; ch < 8; ch += 2) {
                if (ch + 1 < 8) load2(emb4, gbase + (ch + 1) * 2, lane, xb);
                proc2(xa, AhS, linsS, nbase + ch * 2, lane, wlr);
                if (ch + 2 < 8) load2(emb4, gbase + (ch + 2) * 2, lane, xa);
                if (ch + 1 < 8) proc2(xb, AhS, linsS, nbase + (ch + 1) * 2, lane, wlr);
            }
            __threadfence_block();
            bar_arrive(2 + s, 512);                      // signal stage full
        } else {
            bar_sync(2 + s, 512);                        // wait stage full

            const int cw = wid - 8;
            const int wm = (cw >> 2) * 64;
            const int wn = (cw & 3) * 32;
            const int lr = lane & 15;
            const int lk = (lane >> 4) * 8;

            float acc[4][4][4];
            #pragma unroll
            for (int mt = 0; mt < 4; ++mt)
                #pragma unroll
                for (int nt = 0; nt < 4; ++nt)
                    #pragma unroll
                    for (int r = 0; r < 4; ++r) acc[mt][nt][r] = 0.f;

            const uint32_t aAh = sbase + s * STAGE;
            const uint32_t aBh = sbase + SM_B;

            #pragma unroll
            for (int k0 = 0; k0 < 128; k0 += 16) {
                uint32_t bh[4][2];
                #pragma unroll
                for (int nt = 0; nt < 4; ++nt) {
                    uint32_t boff = (uint32_t)(((k0 + lr) * B_STRIDE + wn + nt * 8) * 2);
                    ldsm_x2t(bh[nt], aBh + boff);
                }
                #pragma unroll
                for (int mt = 0; mt < 4; ++mt) {
                    uint32_t aoff = (uint32_t)(((wm + mt * 16 + lr) * A_STRIDE + k0 + lk) * 2);
                    uint32_t ah[4];
                    ldsm_x4(ah, aAh + aoff);
                    #pragma unroll
                    for (int nt = 0; nt < 4; ++nt)
                        mma16816(acc[mt][nt], ah, bh[nt]);
                }
            }

            // epilogue: relu + W2 contraction inside fragments
            const int gid = lane >> 2;
            const int tig = lane & 3;
            float rp[4][2];
            #pragma unroll
            for (int mt = 0; mt < 4; ++mt) { rp[mt][0] = 0.f; rp[mt][1] = 0.f; }

            #pragma unroll
            for (int mt = 0; mt < 4; ++mt)
                #pragma unroll
                for (int nt = 0; nt < 4; ++nt)
                    #pragma unroll
                    for (int r = 0; r < 4; ++r) {
                        int col = wn + nt * 8 + tig * 2 + (r & 1);
                        float hv = acc[mt][nt][r] + b1s[col];
                        rp[mt][r >> 1] = fmaf(fmaxf(hv, 0.f), w2s[col], rp[mt][r >> 1]);
                    }

            #pragma unroll
            for (int mt = 0; mt < 4; ++mt)
                #pragma unroll
                for (int h = 0; h < 2; ++h) {
                    float sum = rp[mt][h];
                    sum += __shfl_xor_sync(0xffffffffu, sum, 1);
                    sum += __shfl_xor_sync(0xffffffffu, sum, 2);
                    if (tig == 0)
                        ps[(wm + mt * 16 + gid + h * 8) * 4 + (cw & 3)] = sum;
                }
            bar_sync(8, 256);                            // consumers only

            int ctid = tid - 256;
            if (ctid < 128) {
                g_v[n0 + ctid] = lins[s * 128 + ctid] + ps[ctid * 4] + ps[ctid * 4 + 1]
                               + ps[ctid * 4 + 2] + ps[ctid * 4 + 3] + cst;
            }
            bar_arrive(5 + s, 512);                      // signal stage empty
        }
    }
}

// ---------------------------------------------------------------------------
// Kernel 2: warp-per-segment aggregation; offsets precomputed in k_node
// ---------------------------------------------------------------------------
#define CAP 1024

__global__ __launch_bounds__(128)
void k_agg(const float* __restrict__ Wm1,
           const float* __restrict__ bm1,
           const float* __restrict__ Wm2,
           const float* __restrict__ bm2,
           float* __restrict__ out)
{
    __shared__ float ssort[4][256];
    __shared__ float sv[CAP];
    __shared__ float red[128];
    __shared__ float aggd[12];
    __shared__ int   dlist[4];
    __shared__ int   dcount;

    const int tid  = threadIdx.x;
    const int lane = tid & 31;
    const int wid  = tid >> 5;
    const int seg  = blockIdx.x * 4 + wid;

    if (tid == 0) dcount = 0;

    // hoist MLP weights into registers (overlaps the g_off->g_v->sort chain)
    float wm1r[12][4], bm1r[4], wm2r[4];
    #pragma unroll
    for (int hh = 0; hh < 4; ++hh) {
        int h = hh * 32 + lane;
        bm1r[hh] = bm1[h];
        wm2r[hh] = Wm2[h];
        #pragma unroll
        for (int i = 0; i < 12; ++i)
            wm1r[i][hh] = Wm1[i * H_DIM + h];
    }
    __syncthreads();

    const int start = g_off[seg];
    const int cnt   = g_off[seg + 1] - start;

    if (cnt > 256) {
        if (lane == 0) { int p = atomicAdd(&dcount, 1); dlist[p] = wid; }
    } else {
        float v[8];
        float sum = 0.f;
        #pragma unroll
        for (int r = 0; r < 8; ++r) {
            int i = r * 32 + lane;
            float x = (i < cnt) ? g_v[start + i] : FLT_MAX;
            v[r] = x;
            if (i < cnt) sum += x;
        }
        #pragma unroll
        for (int d = 16; d > 0; d >>= 1) sum += __shfl_xor_sync(0xffffffffu, sum, d);

        // fixed 256-element bitonic network: idx = r*32 + lane
        #pragma unroll
        for (int k = 2; k <= 256; k <<= 1) {
            #pragma unroll
            for (int j = k >> 1; j > 0; j >>= 1) {
                if (j >= 32) {
                    const int jr = j >> 5;
                    #pragma unroll
                    for (int r = 0; r < 8; ++r) {
                        if ((r & jr) == 0) {
                            int rp = r | jr;
                            bool up = (((r * 32) & k) == 0);
                            float a = v[r], b = v[rp];
                            float lo = fminf(a, b), hi = fmaxf(a, b);
                            v[r]  = up ? lo : hi;
                            v[rp] = up ? hi : lo;
                        }
                    }
                } else {
                    #pragma unroll
                    for (int r = 0; r < 8; ++r) {
                        float other = __shfl_xor_sync(0xffffffffu, v[r], j);
                        bool lower = (lane & j) == 0;
                        bool up = (k < 32) ? ((lane & k) == 0) : (((r * 32) & k) == 0);
                        v[r] = (up == lower) ? fminf(v[r], other) : fmaxf(v[r], other);
                    }
                }
            }
        }

        #pragma unroll
        for (int r = 0; r < 8; ++r) ssort[wid][r * 32 + lane] = v[r];
        __syncwarp();

        float agg[12];
        if (cnt > 0) {
            const float* sw = ssort[wid];
            agg[0] = sum / (float)cnt;
            agg[1] = sw[cnt - 1];
            agg[2] = sw[0];
            #pragma unroll
            for (int qi = 0; qi < 9; ++qi) {
                float q    = (float)(qi + 1) * 0.1f;
                float pos  = q * (float)(cnt - 1);
                float f    = floorf(pos);
                float frac = pos - f;
                int lo = (int)f;
                if (lo > cnt - 1) lo = cnt - 1;
                if (lo < 0) lo = 0;
                int hi = lo + 1;
                if (hi > cnt - 1) hi = cnt - 1;
                agg[3 + qi] = sw[lo] + frac * (sw[hi] - sw[lo]);
            }
        } else {
            #pragma unroll
            for (int i = 0; i < 12; ++i) agg[i] = 0.f;
        }

        // MLP in-warp (weights already in registers)
        float c = 0.f;
        #pragma unroll
        for (int hh = 0; hh < 4; ++hh) {
            float hj = bm1r[hh];
            #pragma unroll
            for (int i = 0; i < 12; ++i)
                hj = fmaf(agg[i], wm1r[i][hh], hj);
            c = fmaf(fmaxf(hj, 0.f), wm2r[hh], c);
        }
        #pragma unroll
        for (int d = 16; d > 0; d >>= 1) c += __shfl_xor_sync(0xffffffffu, c, d);
        if (lane == 0) out[seg] = c + bm2[0];
    }
    __syncthreads();

    // ---- deferred (cnt > 256) segments: block-wide bitonic path ----
    for (int d = 0; d < dcount; ++d) {
        const int dseg   = blockIdx.x * 4 + dlist[d];
        const int dstart = g_off[dseg];
        const int dcnt   = g_off[dseg + 1] - dstart;

        int m = 1;
        while (m < dcnt) m <<= 1;
        if (m > CAP) m = CAP;

        for (int i = tid; i < m; i += 128)
            sv[i] = (i < dcnt && i < CAP) ? g_v[dstart + i] : FLT_MAX;
        __syncthreads();

        for (int ksz = 2; ksz <= m; ksz <<= 1) {
            for (int j = ksz >> 1; j > 0; j >>= 1) {
                for (int i = tid; i < m; i += 128) {
                    int p = i ^ j;
                    if (p > i) {
                        bool up = ((i & ksz) == 0);
                        float x = sv[i], y = sv[p];
                        if (up ? (x > y) : (x < y)) { sv[i] = y; sv[p] = x; }
                    }
                }
                __syncthreads();
            }
        }

        float ls = 0.f;
        for (int i = tid; i < dcnt; i += 128) ls += sv[i];
        red[tid] = ls;
        __syncthreads();
        for (int s = 64; s > 0; s >>= 1) {
            if (tid < s) red[tid] += red[tid + s];
            __syncthreads();
        }
        if (tid == 0) aggd[0] = red[0] / (float)dcnt;
        if (tid == 1) aggd[1] = sv[dcnt - 1];
        if (tid == 2) aggd[2] = sv[0];
        if (tid < 9) {
            float q    = (float)(tid + 1) * 0.1f;
            float pos  = q * (float)(dcnt - 1);
            float f    = floorf(pos);
            float frac = pos - f;
            int lo = (int)f;
            if (lo > dcnt - 1) lo = dcnt - 1;
            if (lo < 0) lo = 0;
            int hi = lo + 1;
            if (hi > dcnt - 1) hi = dcnt - 1;
            aggd[3 + tid] = sv[lo] + frac * (sv[hi] - sv[lo]);
        }
        __syncthreads();

        float contrib = 0.f;
        if (tid < H_DIM) {
            float hj = bm1[tid];
            #pragma unroll
            for (int i = 0; i < 12; ++i)
                hj = fmaf(aggd[i], Wm1[i * H_DIM + tid], hj);
            hj = fmaxf(hj, 0.f);
            contrib = hj * Wm2[tid];
        }
        red[tid] = contrib;
        __syncthreads();
        for (int s = 64; s > 0; s >>= 1) {
            if (tid < s) red[tid] += red[tid + s];
            __syncthreads();
        }
        if (tid == 0) out[dseg] = red[0] + bm2[0];
        __syncthreads();
    }
}

// ---------------------------------------------------------------------------
extern "C" void kernel_launch(void* const* d_in, const int* in_sizes, int n_in,
                              void* d_out, int out_size)
{
    const float4* emb4   = (const float4*)d_in[0];
    const int*    batch  = (const int*)  d_in[1];
    const float*  W_lins = (const float*)d_in[2];
    const float*  b_lins = (const float*)d_in[3];
    const float*  W1     = (const float*)d_in[4];
    const float*  b1     = (const float*)d_in[5];
    const float*  W2     = (const float*)d_in[6];
    const float*  b2     = (const float*)d_in[7];
    const float*  Wm1    = (const float*)d_in[8];
    const float*  bm1    = (const float*)d_in[9];
    const float*  Wm2    = (const float*)d_in[10];
    const float*  bm2    = (const float*)d_in[11];
    float* out = (float*)d_out;

    static int nsm = 0;
    if (nsm == 0) {
        cudaDeviceGetAttribute(&nsm, cudaDevAttrMultiProcessorCount, 0);
        if (nsm <= 0) nsm = 148;
        cudaFuncSetAttribute(k_node, cudaFuncAttributeMaxDynamicSharedMemorySize, SMEM_K1);
    }

    k_node<<<nsm, 512, SMEM_K1>>>(emb4, batch, W_lins, b_lins, W1, b1, W2, b2);
    k_agg<<<B_SEG / 4, 128>>>(Wm1, bm1, Wm2, bm2, out);
}

// round 11
// speedup vs baseline: 1.2035x; 1.2035x over previous
#include <cuda_runtime.h>
#include <cuda_fp16.h>
#include <float.h>
#include <math.h>
#include <cstdint>

#define N_NODES 131072
#define B_SEG   1024
#define H_DIM   128
#define TILE_N  128
#define NTILES  (N_NODES / TILE_N)
#define NSTAGES 3

// Tiles: [128 rows][136 halves] -> 272 B row stride (16B-aligned, 17x16B units)
#define A_STRIDE 136
#define B_STRIDE 136

__device__ float g_v[N_NODES];
__device__ int   g_off[B_SEG + 1];

// ---- k_node smem layout (bytes) ----
static constexpr int STAGE   = 34816;                   // Ah per stage
static constexpr int SM_B    = NSTAGES * STAGE;         // 104448
static constexpr int SM_FLT  = SM_B + 34816;            // 139264
// floats: lins[3][128], ps[512], b1s[128], w2s[128] = 1152 floats
static constexpr int SMEM_K1 = SM_FLT + 1152 * 4;       // 143872

// ---------------------------------------------------------------------------
__device__ __forceinline__ uint32_t smem_u32(const void* p) {
    uint32_t a;
    asm("{ .reg .u64 t; cvta.to.shared.u64 t, %1; cvt.u32.u64 %0, t; }"
        : "=r"(a) : "l"(p));
    return a;
}
__device__ __forceinline__ void bar_sync(int id, int cnt) {
    asm volatile("bar.sync %0, %1;" :: "r"(id), "r"(cnt) : "memory");
}
__device__ __forceinline__ void bar_arrive(int id, int cnt) {
    asm volatile("bar.arrive %0, %1;" :: "r"(id), "r"(cnt) : "memory");
}
__device__ __forceinline__ void ldsm_x4(uint32_t* r, uint32_t a) {
    asm volatile("ldmatrix.sync.aligned.m8n8.x4.shared.b16 {%0,%1,%2,%3}, [%4];"
                 : "=r"(r[0]), "=r"(r[1]), "=r"(r[2]), "=r"(r[3]) : "r"(a));
}
__device__ __forceinline__ void ldsm_x2t(uint32_t* r, uint32_t a) {
    asm volatile("ldmatrix.sync.aligned.m8n8.x2.trans.shared.b16 {%0,%1}, [%2];"
                 : "=r"(r[0]), "=r"(r[1]) : "r"(a));
}
__device__ __forceinline__ void mma16816(float* d, const uint32_t* a, const uint32_t* b) {
    asm volatile(
        "mma.sync.aligned.m16n8k16.row.col.f32.f16.f16.f32 "
        "{%0,%1,%2,%3}, {%4,%5,%6,%7}, {%8,%9}, {%0,%1,%2,%3};"
        : "+f"(d[0]), "+f"(d[1]), "+f"(d[2]), "+f"(d[3])
        : "r"(a[0]), "r"(a[1]), "r"(a[2]), "r"(a[3]), "r"(b[0]), "r"(b[1]));
}

// producer helpers — CONTIGUOUS layout: lane covers c = cc*32 + lane
// (each LDG.128 warp-access = 512 B contiguous, 4 L1 wavefronts)
__device__ __forceinline__ void loadC(const float4* __restrict__ emb4, size_t ng,
                                      int lane, float4 x[2][4]) {
    #pragma unroll
    for (int k = 0; k < 2; ++k) {
        const float4* p = emb4 + (ng + k) * 128 + lane;
        x[k][0] = p[0];
        x[k][1] = p[32];
        x[k][2] = p[64];
        x[k][3] = p[96];
    }
}

__device__ __forceinline__ void procC(const float4 x[2][4], char* AhS, float* linsS,
                                      int nl, int lane, const float wlr[3][4]) {
    #pragma unroll
    for (int k = 0; k < 2; ++k) {
        float l = 0.f;
        #pragma unroll
        for (int cc = 0; cc < 4; ++cc) {
            int c = cc * 32 + lane;
            l = fmaf(x[k][cc].x, wlr[0][cc], l);
            l = fmaf(x[k][cc].y, wlr[1][cc], l);
            l = fmaf(x[k][cc].z, wlr[2][cc], l);
            *(__half*)(AhS + ((nl + k) * A_STRIDE + c) * 2) =
                __float2half_rn(x[k][cc].w);
        }
        #pragma unroll
        for (int d = 16; d > 0; d >>= 1)
            l += __shfl_xor_sync(0xffffffffu, l, d);
        if (lane == 0) linsS[nl + k] = l;
    }
}

// ---------------------------------------------------------------------------
// Kernel 1: persistent warp-specialized node readout (fp16 single-term MMA)
//   producers (warps 0-7): ping-pong pipelined load + lin + fp16 A -> ring
//   consumers (warps 8-15): mma.sync GEMM + relu+W2 epilogue
// ---------------------------------------------------------------------------
__global__ __launch_bounds__(512, 1)
void k_node(const float4* __restrict__ emb4,
            const int*    __restrict__ batch,
            const float*  __restrict__ W_lins,
            const float*  __restrict__ b_lins,
            const float*  __restrict__ W1,
            const float*  __restrict__ b1,
            const float*  __restrict__ W2,
            const float*  __restrict__ b2)
{
    extern __shared__ __align__(16) char smem[];
    char*  Bh   = smem + SM_B;
    float* lins = (float*)(smem + SM_FLT);   // [3][128]
    float* ps   = lins + NSTAGES * 128;      // [128][4]
    float* b1s  = ps + 512;                  // [128]
    float* w2s  = b1s + 128;                 // [128]

    const int tid  = threadIdx.x;
    const int lane = tid & 31;
    const int wid  = tid >> 5;
    const bool producer = (wid < 8);
    const uint32_t sbase = smem_u32(smem);

    // ---- prelude: segment-offset scatter (batch sorted) ----
    for (int i = blockIdx.x * 512 + tid; i < N_NODES; i += gridDim.x * 512) {
        int b    = batch[i];
        int prev = (i == 0) ? -1 : batch[i - 1];
        for (int bb = prev + 1; bb <= b; ++bb) g_off[bb] = i;
        if (i == N_NODES - 1)
            for (int bb = b + 1; bb <= B_SEG; ++bb) g_off[bb] = N_NODES;
    }

    // one-time staging: W1 -> fp16 B tile, b1s, w2s
    for (int i = tid; i < 128 * 128 / 4; i += 512) {
        float4 w = ((const float4*)W1)[i];
        int c  = i >> 5;
        int h4 = (i & 31) * 4;
        int off = (c * B_STRIDE + h4) * 2;
        *(__half2*)(Bh + off)     = __floats2half2_rn(w.x, w.y);
        *(__half2*)(Bh + off + 4) = __floats2half2_rn(w.z, w.w);
    }
    if (tid < 128) { b1s[tid] = b1[tid]; w2s[tid] = W2[tid]; }

    // producers: W_lins at contiguous positions (c = cc*32 + lane)
    float wlr[3][4];
    if (producer) {
        #pragma unroll
        for (int r = 0; r < 3; ++r)
            #pragma unroll
            for (int cc = 0; cc < 4; ++cc)
                wlr[r][cc] = W_lins[r * 128 + cc * 32 + lane];
    }
    const float cst = b_lins[0] + b_lins[1] + b_lins[2] + b2[0];
    __syncthreads();

    int it = 0;
    for (int t = blockIdx.x; t < NTILES; t += gridDim.x, ++it) {
        const int s  = it % NSTAGES;
        const int n0 = t * TILE_N;

        if (producer) {
            if (it >= NSTAGES) bar_sync(5 + s, 512);     // wait stage empty
            char*  AhS   = smem + s * STAGE;
            float* linsS = lins + s * 128;
            const int nbase = wid * 16;
            const size_t gbase = (size_t)(n0 + nbase);

            // ping-pong pipelined 2-node chunks (8 chunks)
            float4 xa[2][4], xb[2][4];
            loadC(emb4, gbase, lane, xa);
            #pragma unroll
            for (int ch = 0; ch < 8; ch += 2) {
                if (ch + 1 < 8) loadC(emb4, gbase + (ch + 1) * 2, lane, xb);
                procC(xa, AhS, linsS, nbase + ch * 2, lane, wlr);
                if (ch + 2 < 8) loadC(emb4, gbase + (ch + 2) * 2, lane, xa);
                if (ch + 1 < 8) procC(xb, AhS, linsS, nbase + (ch + 1) * 2, lane, wlr);
            }
            __threadfence_block();
            bar_arrive(2 + s, 512);                      // signal stage full
        } else {
            bar_sync(2 + s, 512);                        // wait stage full

            const int cw = wid - 8;
            const int wm = (cw >> 2) * 64;
            const int wn = (cw & 3) * 32;
            const int lr = lane & 15;
            const int lk = (lane >> 4) * 8;

            float acc[4][4][4];
            #pragma unroll
            for (int mt = 0; mt < 4; ++mt)
                #pragma unroll
                for (int nt = 0; nt < 4; ++nt)
                    #pragma unroll
                    for (int r = 0; r < 4; ++r) acc[mt][nt][r] = 0.f;

            const uint32_t aAh = sbase + s * STAGE;
            const uint32_t aBh = sbase + SM_B;

            #pragma unroll
            for (int k0 = 0; k0 < 128; k0 += 16) {
                uint32_t bh[4][2];
                #pragma unroll
                for (int nt = 0; nt < 4; ++nt) {
                    uint32_t boff = (uint32_t)(((k0 + lr) * B_STRIDE + wn + nt * 8) * 2);
                    ldsm_x2t(bh[nt], aBh + boff);
                }
                #pragma unroll
                for (int mt = 0; mt < 4; ++mt) {
                    uint32_t aoff = (uint32_t)(((wm + mt * 16 + lr) * A_STRIDE + k0 + lk) * 2);
                    uint32_t ah[4];
                    ldsm_x4(ah, aAh + aoff);
                    #pragma unroll
                    for (int nt = 0; nt < 4; ++nt)
                        mma16816(acc[mt][nt], ah, bh[nt]);
                }
            }

            // epilogue: relu + W2 contraction inside fragments
            const int gid = lane >> 2;
            const int tig = lane & 3;
            float rp[4][2];
            #pragma unroll
            for (int mt = 0; mt < 4; ++mt) { rp[mt][0] = 0.f; rp[mt][1] = 0.f; }

            #pragma unroll
            for (int mt = 0; mt < 4; ++mt)
                #pragma unroll
                for (int nt = 0; nt < 4; ++nt)
                    #pragma unroll
                    for (int r = 0; r < 4; ++r) {
                        int col = wn + nt * 8 + tig * 2 + (r & 1);
                        float hv = acc[mt][nt][r] + b1s[col];
                        rp[mt][r >> 1] = fmaf(fmaxf(hv, 0.f), w2s[col], rp[mt][r >> 1]);
                    }

            #pragma unroll
            for (int mt = 0; mt < 4; ++mt)
                #pragma unroll
                for (int h = 0; h < 2; ++h) {
                    float sum = rp[mt][h];
                    sum += __shfl_xor_sync(0xffffffffu, sum, 1);
                    sum += __shfl_xor_sync(0xffffffffu, sum, 2);
                    if (tig == 0)
                        ps[(wm + mt * 16 + gid + h * 8) * 4 + (cw & 3)] = sum;
                }
            bar_sync(8, 256);                            // consumers only

            int ctid = tid - 256;
            if (ctid < 128) {
                g_v[n0 + ctid] = lins[s * 128 + ctid] + ps[ctid * 4] + ps[ctid * 4 + 1]
                               + ps[ctid * 4 + 2] + ps[ctid * 4 + 3] + cst;
            }
            bar_arrive(5 + s, 512);                      // signal stage empty
        }
    }
}

// ---------------------------------------------------------------------------
// Kernel 2: warp-per-segment aggregation; offsets precomputed in k_node
// ---------------------------------------------------------------------------
#define CAP 1024

__global__ __launch_bounds__(128)
void k_agg(const float* __restrict__ Wm1,
           const float* __restrict__ bm1,
           const float* __restrict__ Wm2,
           const float* __restrict__ bm2,
           float* __restrict__ out)
{
    __shared__ float ssort[4][256];
    __shared__ float sv[CAP];
    __shared__ float red[128];
    __shared__ float aggd[12];
    __shared__ int   dlist[4];
    __shared__ int   dcount;

    const int tid  = threadIdx.x;
    const int lane = tid & 31;
    const int wid  = tid >> 5;
    const int seg  = blockIdx.x * 4 + wid;

    if (tid == 0) dcount = 0;

    // hoist MLP weights into registers (overlaps the g_off->g_v->sort chain)
    float wm1r[12][4], bm1r[4], wm2r[4];
    #pragma unroll
    for (int hh = 0; hh < 4; ++hh) {
        int h = hh * 32 + lane;
        bm1r[hh] = bm1[h];
        wm2r[hh] = Wm2[h];
        #pragma unroll
        for (int i = 0; i < 12; ++i)
            wm1r[i][hh] = Wm1[i * H_DIM + h];
    }
    __syncthreads();

    const int start = g_off[seg];
    const int cnt   = g_off[seg + 1] - start;

    if (cnt > 256) {
        if (lane == 0) { int p = atomicAdd(&dcount, 1); dlist[p] = wid; }
    } else {
        float v[8];
        float sum = 0.f;
        #pragma unroll
        for (int r = 0; r < 8; ++r) {
            int i = r * 32 + lane;
            float x = (i < cnt) ? g_v[start + i] : FLT_MAX;
            v[r] = x;
            if (i < cnt) sum += x;
        }
        #pragma unroll
        for (int d = 16; d > 0; d >>= 1) sum += __shfl_xor_sync(0xffffffffu, sum, d);

        // fixed 256-element bitonic network: idx = r*32 + lane
        #pragma unroll
        for (int k = 2; k <= 256; k <<= 1) {
            #pragma unroll
            for (int j = k >> 1; j > 0; j >>= 1) {
                if (j >= 32) {
                    const int jr = j >> 5;
                    #pragma unroll
                    for (int r = 0; r < 8; ++r) {
                        if ((r & jr) == 0) {
                            int rp = r | jr;
                            bool up = (((r * 32) & k) == 0);
                            float a = v[r], b = v[rp];
                            float lo = fminf(a, b), hi = fmaxf(a, b);
                            v[r]  = up ? lo : hi;
                            v[rp] = up ? hi : lo;
                        }
                    }
                } else {
                    #pragma unroll
                    for (int r = 0; r < 8; ++r) {
                        float other = __shfl_xor_sync(0xffffffffu, v[r], j);
                        bool lower = (lane & j) == 0;
                        bool up = (k < 32) ? ((lane & k) == 0) : (((r * 32) & k) == 0);
                        v[r] = (up == lower) ? fminf(v[r], other) : fmaxf(v[r], other);
                    }
                }
            }
        }

        #pragma unroll
        for (int r = 0; r < 8; ++r) ssort[wid][r * 32 + lane] = v[r];
        __syncwarp();

        float agg[12];
        if (cnt > 0) {
            const float* sw = ssort[wid];
            agg[0] = sum / (float)cnt;
            agg[1] = sw[cnt - 1];
            agg[2] = sw[0];
            #pragma unroll
            for (int qi = 0; qi < 9; ++qi) {
                float q    = (float)(qi + 1) * 0.1f;
                float pos  = q * (float)(cnt - 1);
                float f    = floorf(pos);
                float frac = pos - f;
                int lo = (int)f;
                if (lo > cnt - 1) lo = cnt - 1;
                if (lo < 0) lo = 0;
                int hi = lo + 1;
                if (hi > cnt - 1) hi = cnt - 1;
                agg[3 + qi] = sw[lo] + frac * (sw[hi] - sw[lo]);
            }
        } else {
            #pragma unroll
            for (int i = 0; i < 12; ++i) agg[i] = 0.f;
        }

        // MLP in-warp (weights already in registers)
        float c = 0.f;
        #pragma unroll
        for (int hh = 0; hh < 4; ++hh) {
            float hj = bm1r[hh];
            #pragma unroll
            for (int i = 0; i < 12; ++i)
                hj = fmaf(agg[i], wm1r[i][hh], hj);
            c = fmaf(fmaxf(hj, 0.f), wm2r[hh], c);
        }
        #pragma unroll
        for (int d = 16; d > 0; d >>= 1) c += __shfl_xor_sync(0xffffffffu, c, d);
        if (lane == 0) out[seg] = c + bm2[0];
    }
    __syncthreads();

    // ---- deferred (cnt > 256) segments: block-wide bitonic path ----
    for (int d = 0; d < dcount; ++d) {
        const int dseg   = blockIdx.x * 4 + dlist[d];
        const int dstart = g_off[dseg];
        const int dcnt   = g_off[dseg + 1] - dstart;

        int m = 1;
        while (m < dcnt) m <<= 1;
        if (m > CAP) m = CAP;

        for (int i = tid; i < m; i += 128)
            sv[i] = (i < dcnt && i < CAP) ? g_v[dstart + i] : FLT_MAX;
        __syncthreads();

        for (int ksz = 2; ksz <= m; ksz <<= 1) {
            for (int j = ksz >> 1; j > 0; j >>= 1) {
                for (int i = tid; i < m; i += 128) {
                    int p = i ^ j;
                    if (p > i) {
                        bool up = ((i & ksz) == 0);
                        float x = sv[i], y = sv[p];
                        if (up ? (x > y) : (x < y)) { sv[i] = y; sv[p] = x; }
                    }
                }
                __syncthreads();
            }
        }

        float ls = 0.f;
        for (int i = tid; i < dcnt; i += 128) ls += sv[i];
        red[tid] = ls;
        __syncthreads();
        for (int s = 64; s > 0; s >>= 1) {
            if (tid < s) red[tid] += red[tid + s];
            __syncthreads();
        }
        if (tid == 0) aggd[0] = red[0] / (float)dcnt;
        if (tid == 1) aggd[1] = sv[dcnt - 1];
        if (tid == 2) aggd[2] = sv[0];
        if (tid < 9) {
            float q    = (float)(tid + 1) * 0.1f;
            float pos  = q * (float)(dcnt - 1);
            float f    = floorf(pos);
            float frac = pos - f;
            int lo = (int)f;
            if (lo > dcnt - 1) lo = dcnt - 1;
            if (lo < 0) lo = 0;
            int hi = lo + 1;
            if (hi > dcnt - 1) hi = dcnt - 1;
            aggd[3 + tid] = sv[lo] + frac * (sv[hi] - sv[lo]);
        }
        __syncthreads();

        float contrib = 0.f;
        if (tid < H_DIM) {
            float hj = bm1[tid];
            #pragma unroll
            for (int i = 0; i < 12; ++i)
                hj = fmaf(aggd[i], Wm1[i * H_DIM + tid], hj);
            hj = fmaxf(hj, 0.f);
            contrib = hj * Wm2[tid];
        }
        red[tid] = contrib;
        __syncthreads();
        for (int s = 64; s > 0; s >>= 1) {
            if (tid < s) red[tid] += red[tid + s];
            __syncthreads();
        }
        if (tid == 0) out[dseg] = red[0] + bm2[0];
        __syncthreads();
    }
}

// ---------------------------------------------------------------------------
extern "C" void kernel_launch(void* const* d_in, const int* in_sizes, int n_in,
                              void* d_out, int out_size)
{
    const float4* emb4   = (const float4*)d_in[0];
    const int*    batch  = (const int*)  d_in[1];
    const float*  W_lins = (const float*)d_in[2];
    const float*  b_lins = (const float*)d_in[3];
    const float*  W1     = (const float*)d_in[4];
    const float*  b1     = (const float*)d_in[5];
    const float*  W2     = (const float*)d_in[6];
    const float*  b2     = (const float*)d_in[7];
    const float*  Wm1    = (const float*)d_in[8];
    const float*  bm1    = (const float*)d_in[9];
    const float*  Wm2    = (const float*)d_in[10];
    const float*  bm2    = (const float*)d_in[11];
    float* out = (float*)d_out;

    static int nsm = 0;
    if (nsm == 0) {
        cudaDeviceGetAttribute(&nsm, cudaDevAttrMultiProcessorCount, 0);
        if (nsm <= 0) nsm = 148;
        cudaFuncSetAttribute(k_node, cudaFuncAttributeMaxDynamicSharedMemorySize, SMEM_K1);
    }

    k_node<<<nsm, 512, SMEM_K1>>>(emb4, batch, W_lins, b_lins, W1, b1, W2, b2);
    k_agg<<<B_SEG / 4, 128>>>(Wm1, bm1, Wm2, bm2, out);
}

// round 12
// speedup vs baseline: 1.4338x; 1.1913x over previous
#include <cuda_runtime.h>
#include <cuda_fp16.h>
#include <float.h>
#include <math.h>
#include <cstdint>

#define N_NODES 131072
#define B_SEG   1024
#define H_DIM   128
#define TILE_N  128
#define NTILES  (N_NODES / TILE_N)
#define NSTAGES 2

// Tiles: [128 rows][136 halves] -> 272 B row stride (16B-aligned, 17x16B units)
#define A_STRIDE 136
#define B_STRIDE 136

__device__ float g_v[N_NODES];
__device__ int   g_off[B_SEG + 1];

// ---- k_node smem layout (bytes) ----
static constexpr int STAGE   = 34816;                   // A fp16 tile per stage
static constexpr int SM_B    = NSTAGES * STAGE;         // 69632
static constexpr int SM_FLT  = SM_B + 34816;            // 104448
// floats: lins[2][128]=256, ps[128][4]=512 -> 768 floats
static constexpr int SMEM_K1 = SM_FLT + 768 * 4;        // 107520

// ---------------------------------------------------------------------------
__device__ __forceinline__ uint32_t smem_u32(const void* p) {
    uint32_t a;
    asm("{ .reg .u64 t; cvta.to.shared.u64 t, %1; cvt.u32.u64 %0, t; }"
        : "=r"(a) : "l"(p));
    return a;
}
__device__ __forceinline__ void ldsm_x4(uint32_t* r, uint32_t a) {
    asm volatile("ldmatrix.sync.aligned.m8n8.x4.shared.b16 {%0,%1,%2,%3}, [%4];"
                 : "=r"(r[0]), "=r"(r[1]), "=r"(r[2]), "=r"(r[3]) : "r"(a));
}
__device__ __forceinline__ void ldsm_x2t(uint32_t* r, uint32_t a) {
    asm volatile("ldmatrix.sync.aligned.m8n8.x2.trans.shared.b16 {%0,%1}, [%2];"
                 : "=r"(r[0]), "=r"(r[1]) : "r"(a));
}
__device__ __forceinline__ void mma16816(float* d, const uint32_t* a, const uint32_t* b) {
    asm volatile(
        "mma.sync.aligned.m16n8k16.row.col.f32.f16.f16.f32 "
        "{%0,%1,%2,%3}, {%4,%5,%6,%7}, {%8,%9}, {%0,%1,%2,%3};"
        : "+f"(d[0]), "+f"(d[1]), "+f"(d[2]), "+f"(d[3])
        : "r"(a[0]), "r"(a[1]), "r"(a[2]), "r"(a[3]), "r"(b[0]), "r"(b[1]));
}

// ---------------------------------------------------------------------------
// Kernel 1: persistent SYMMETRIC node readout (all 16 warps load AND mma)
// ---------------------------------------------------------------------------
__global__ __launch_bounds__(512, 1)
void k_node(const float4* __restrict__ emb4,
            const int*    __restrict__ batch,
            const float*  __restrict__ W_lins,
            const float*  __restrict__ b_lins,
            const float*  __restrict__ W1,
            const float*  __restrict__ b1,
            const float*  __restrict__ W2,
            const float*  __restrict__ b2)
{
    extern __shared__ __align__(16) char smem[];
    char*  Bh   = smem + SM_B;
    float* lins = (float*)(smem + SM_FLT);   // [2][128]
    float* ps   = lins + NSTAGES * 128;      // [128][4]

    const int tid  = threadIdx.x;
    const int lane = tid & 31;
    const int wid  = tid >> 5;
    const uint32_t sbase = smem_u32(smem);

    // ---- prelude: segment-offset scatter (batch sorted) ----
    for (int i = blockIdx.x * 512 + tid; i < N_NODES; i += gridDim.x * 512) {
        int b    = batch[i];
        int prev = (i == 0) ? -1 : batch[i - 1];
        for (int bb = prev + 1; bb <= b; ++bb) g_off[bb] = i;
        if (i == N_NODES - 1)
            for (int bb = b + 1; bb <= B_SEG; ++bb) g_off[bb] = N_NODES;
    }

    // one-time staging: W1 -> fp16 B tile
    for (int i = tid; i < 128 * 128 / 4; i += 512) {
        float4 w = ((const float4*)W1)[i];
        int c  = i >> 5;
        int h4 = (i & 31) * 4;
        int off = (c * B_STRIDE + h4) * 2;
        *(__half2*)(Bh + off)     = __floats2half2_rn(w.x, w.y);
        *(__half2*)(Bh + off + 4) = __floats2half2_rn(w.z, w.w);
    }

    // per-lane constants
    float wlr[3][4];
    #pragma unroll
    for (int r = 0; r < 3; ++r)
        #pragma unroll
        for (int cc = 0; cc < 4; ++cc)
            wlr[r][cc] = W_lins[r * 128 + cc * 32 + lane];

    // MMA warp tile: rows wm*32, cols wn*32
    const int wm = wid >> 2;
    const int wn = wid & 3;
    const int lr = lane & 15;
    const int lk = (lane >> 4) * 8;
    const int gid = lane >> 2;
    const int tig = lane & 3;

    // epilogue constants for this lane's 8 columns: col = wn*32 + nt*8 + tig*2 + j
    float b1r[4][2], w2r[4][2];
    #pragma unroll
    for (int nt = 0; nt < 4; ++nt)
        #pragma unroll
        for (int j = 0; j < 2; ++j) {
            int col = wn * 32 + nt * 8 + tig * 2 + j;
            b1r[nt][j] = b1[col];
            w2r[nt][j] = W2[col];
        }
    const float cst = b_lins[0] + b_lins[1] + b_lins[2] + b2[0];
    __syncthreads();

    int it = 0;
    for (int t = blockIdx.x; t < NTILES; t += gridDim.x, ++it) {
        const int s  = it & 1;
        const int n0 = t * TILE_N;
        char*  AhS   = smem + s * STAGE;
        float* linsS = lins + s * 128;

        // ---- load/convert phase: warp owns nodes wid*8 .. wid*8+7 ----
        #pragma unroll 1
        for (int ch = 0; ch < 4; ++ch) {
            int nl = wid * 8 + ch * 2;
            float4 x[2][4];
            #pragma unroll
            for (int k = 0; k < 2; ++k) {
                const float4* p = emb4 + (size_t)(n0 + nl + k) * 128 + lane;
                x[k][0] = p[0];
                x[k][1] = p[32];
                x[k][2] = p[64];
                x[k][3] = p[96];
            }
            #pragma unroll
            for (int k = 0; k < 2; ++k) {
                float l = 0.f;
                #pragma unroll
                for (int cc = 0; cc < 4; ++cc) {
                    int c = cc * 32 + lane;
                    l = fmaf(x[k][cc].x, wlr[0][cc], l);
                    l = fmaf(x[k][cc].y, wlr[1][cc], l);
                    l = fmaf(x[k][cc].z, wlr[2][cc], l);
                    *(__half*)(AhS + ((nl + k) * A_STRIDE + c) * 2) =
                        __float2half_rn(x[k][cc].w);
                }
                #pragma unroll
                for (int d = 16; d > 0; d >>= 1)
                    l += __shfl_xor_sync(0xffffffffu, l, d);
                if (lane == 0) linsS[nl + k] = l;
            }
        }
        __syncthreads();                         // stage s full

        // ---- MMA phase: warp computes 32x32 block ----
        float acc[2][4][4];
        #pragma unroll
        for (int mt = 0; mt < 2; ++mt)
            #pragma unroll
            for (int nt = 0; nt < 4; ++nt)
                #pragma unroll
                for (int r = 0; r < 4; ++r) acc[mt][nt][r] = 0.f;

        const uint32_t aA = sbase + s * STAGE;
        const uint32_t aB = sbase + SM_B;

        #pragma unroll
        for (int k0 = 0; k0 < 128; k0 += 16) {
            uint32_t bh[4][2];
            #pragma unroll
            for (int nt = 0; nt < 4; ++nt) {
                uint32_t boff = (uint32_t)(((k0 + lr) * B_STRIDE + wn * 32 + nt * 8) * 2);
                ldsm_x2t(bh[nt], aB + boff);
            }
            #pragma unroll
            for (int mt = 0; mt < 2; ++mt) {
                uint32_t aoff = (uint32_t)(((wm * 32 + mt * 16 + lr) * A_STRIDE + k0 + lk) * 2);
                uint32_t ah[4];
                ldsm_x4(ah, aA + aoff);
                #pragma unroll
                for (int nt = 0; nt < 4; ++nt)
                    mma16816(acc[mt][nt], ah, bh[nt]);
            }
        }

        // epilogue: relu + W2 contraction inside fragments
        float rp[2][2];
        rp[0][0] = rp[0][1] = rp[1][0] = rp[1][1] = 0.f;
        #pragma unroll
        for (int mt = 0; mt < 2; ++mt)
            #pragma unroll
            for (int nt = 0; nt < 4; ++nt)
                #pragma unroll
                for (int r = 0; r < 4; ++r) {
                    float hv = acc[mt][nt][r] + b1r[nt][r & 1];
                    rp[mt][r >> 1] = fmaf(fmaxf(hv, 0.f), w2r[nt][r & 1], rp[mt][r >> 1]);
                }
        #pragma unroll
        for (int mt = 0; mt < 2; ++mt)
            #pragma unroll
            for (int h = 0; h < 2; ++h) {
                float sum = rp[mt][h];
                sum += __shfl_xor_sync(0xffffffffu, sum, 1);
                sum += __shfl_xor_sync(0xffffffffu, sum, 2);
                if (tig == 0)
                    ps[(wm * 32 + mt * 16 + gid + h * 8) * 4 + wn] = sum;
            }
        __syncthreads();                         // ps + lins ready

        if (tid < 128) {
            g_v[n0 + tid] = linsS[tid] + ps[tid * 4] + ps[tid * 4 + 1]
                          + ps[tid * 4 + 2] + ps[tid * 4 + 3] + cst;
        }
        // next iteration writes stage s^1 (last read two iterations ago) - safe
    }
}

// ---------------------------------------------------------------------------
// Kernel 2: warp-per-segment aggregation; offsets precomputed in k_node
// ---------------------------------------------------------------------------
#define CAP 1024

__global__ __launch_bounds__(128)
void k_agg(const float* __restrict__ Wm1,
           const float* __restrict__ bm1,
           const float* __restrict__ Wm2,
           const float* __restrict__ bm2,
           float* __restrict__ out)
{
    __shared__ float ssort[4][256];
    __shared__ float sv[CAP];
    __shared__ float red[128];
    __shared__ float aggd[12];
    __shared__ int   dlist[4];
    __shared__ int   dcount;

    const int tid  = threadIdx.x;
    const int lane = tid & 31;
    const int wid  = tid >> 5;
    const int seg  = blockIdx.x * 4 + wid;

    if (tid == 0) dcount = 0;

    // hoist MLP weights into registers (overlaps the g_off->g_v->sort chain)
    float wm1r[12][4], bm1r[4], wm2r[4];
    #pragma unroll
    for (int hh = 0; hh < 4; ++hh) {
        int h = hh * 32 + lane;
        bm1r[hh] = bm1[h];
        wm2r[hh] = Wm2[h];
        #pragma unroll
        for (int i = 0; i < 12; ++i)
            wm1r[i][hh] = Wm1[i * H_DIM + h];
    }
    __syncthreads();

    const int start = g_off[seg];
    const int cnt   = g_off[seg + 1] - start;

    if (cnt > 256) {
        if (lane == 0) { int p = atomicAdd(&dcount, 1); dlist[p] = wid; }
    } else {
        float v[8];
        float sum = 0.f;
        #pragma unroll
        for (int r = 0; r < 8; ++r) {
            int i = r * 32 + lane;
            float x = (i < cnt) ? g_v[start + i] : FLT_MAX;
            v[r] = x;
            if (i < cnt) sum += x;
        }
        #pragma unroll
        for (int d = 16; d > 0; d >>= 1) sum += __shfl_xor_sync(0xffffffffu, sum, d);

        // fixed 256-element bitonic network: idx = r*32 + lane
        #pragma unroll
        for (int k = 2; k <= 256; k <<= 1) {
            #pragma unroll
            for (int j = k >> 1; j > 0; j >>= 1) {
                if (j >= 32) {
                    const int jr = j >> 5;
                    #pragma unroll
                    for (int r = 0; r < 8; ++r) {
                        if ((r & jr) == 0) {
                            int rp = r | jr;
                            bool up = (((r * 32) & k) == 0);
                            float a = v[r], b = v[rp];
                            float lo = fminf(a, b), hi = fmaxf(a, b);
                            v[r]  = up ? lo : hi;
                            v[rp] = up ? hi : lo;
                        }
                    }
                } else {
                    #pragma unroll
                    for (int r = 0; r < 8; ++r) {
                        float other = __shfl_xor_sync(0xffffffffu, v[r], j);
                        bool lower = (lane & j) == 0;
                        bool up = (k < 32) ? ((lane & k) == 0) : (((r * 32) & k) == 0);
                        v[r] = (up == lower) ? fminf(v[r], other) : fmaxf(v[r], other);
                    }
                }
            }
        }

        #pragma unroll
        for (int r = 0; r < 8; ++r) ssort[wid][r * 32 + lane] = v[r];
        __syncwarp();

        float agg[12];
        if (cnt > 0) {
            const float* sw = ssort[wid];
            agg[0] = sum / (float)cnt;
            agg[1] = sw[cnt - 1];
            agg[2] = sw[0];
            #pragma unroll
            for (int qi = 0; qi < 9; ++qi) {
                float q    = (float)(qi + 1) * 0.1f;
                float pos  = q * (float)(cnt - 1);
                float f    = floorf(pos);
                float frac = pos - f;
                int lo = (int)f;
                if (lo > cnt - 1) lo = cnt - 1;
                if (lo < 0) lo = 0;
                int hi = lo + 1;
                if (hi > cnt - 1) hi = cnt - 1;
                agg[3 + qi] = sw[lo] + frac * (sw[hi] - sw[lo]);
            }
        } else {
            #pragma unroll
            for (int i = 0; i < 12; ++i) agg[i] = 0.f;
        }

        // MLP in-warp (weights already in registers)
        float c = 0.f;
        #pragma unroll
        for (int hh = 0; hh < 4; ++hh) {
            float hj = bm1r[hh];
            #pragma unroll
            for (int i = 0; i < 12; ++i)
                hj = fmaf(agg[i], wm1r[i][hh], hj);
            c = fmaf(fmaxf(hj, 0.f), wm2r[hh], c);
        }
        #pragma unroll
        for (int d = 16; d > 0; d >>= 1) c += __shfl_xor_sync(0xffffffffu, c, d);
        if (lane == 0) out[seg] = c + bm2[0];
    }
    __syncthreads();

    // ---- deferred (cnt > 256) segments: block-wide bitonic path ----
    for (int d = 0; d < dcount; ++d) {
        const int dseg   = blockIdx.x * 4 + dlist[d];
        const int dstart = g_off[dseg];
        const int dcnt   = g_off[dseg + 1] - dstart;

        int m = 1;
        while (m < dcnt) m <<= 1;
        if (m > CAP) m = CAP;

        for (int i = tid; i < m; i += 128)
            sv[i] = (i < dcnt && i < CAP) ? g_v[dstart + i] : FLT_MAX;
        __syncthreads();

        for (int ksz = 2; ksz <= m; ksz <<= 1) {
            for (int j = ksz >> 1; j > 0; j >>= 1) {
                for (int i = tid; i < m; i += 128) {
                    int p = i ^ j;
                    if (p > i) {
                        bool up = ((i & ksz) == 0);
                        float x = sv[i], y = sv[p];
                        if (up ? (x > y) : (x < y)) { sv[i] = y; sv[p] = x; }
                    }
                }
                __syncthreads();
            }
        }

        float ls = 0.f;
        for (int i = tid; i < dcnt; i += 128) ls += sv[i];
        red[tid] = ls;
        __syncthreads();
        for (int s = 64; s > 0; s >>= 1) {
            if (tid < s) red[tid] += red[tid + s];
            __syncthreads();
        }
        if (tid == 0) aggd[0] = red[0] / (float)dcnt;
        if (tid == 1) aggd[1] = sv[dcnt - 1];
        if (tid == 2) aggd[2] = sv[0];
        if (tid < 9) {
            float q    = (float)(tid + 1) * 0.1f;
            float pos  = q * (float)(dcnt - 1);
            float f    = floorf(pos);
            float frac = pos - f;
            int lo = (int)f;
            if (lo > dcnt - 1) lo = dcnt - 1;
            if (lo < 0) lo = 0;
            int hi = lo + 1;
            if (hi > dcnt - 1) hi = dcnt - 1;
            aggd[3 + tid] = sv[lo] + frac * (sv[hi] - sv[lo]);
        }
        __syncthreads();

        float contrib = 0.f;
        if (tid < H_DIM) {
            float hj = bm1[tid];
            #pragma unroll
            for (int i = 0; i < 12; ++i)
                hj = fmaf(aggd[i], Wm1[i * H_DIM + tid], hj);
            hj = fmaxf(hj, 0.f);
            contrib = hj * Wm2[tid];
        }
        red[tid] = contrib;
        __syncthreads();
        for (int s = 64; s > 0; s >>= 1) {
            if (tid < s) red[tid] += red[tid + s];
            __syncthreads();
        }
        if (tid == 0) out[dseg] = red[0] + bm2[0];
        __syncthreads();
    }
}

// ---------------------------------------------------------------------------
extern "C" void kernel_launch(void* const* d_in, const int* in_sizes, int n_in,
                              void* d_out, int out_size)
{
    const float4* emb4   = (const float4*)d_in[0];
    const int*    batch  = (const int*)  d_in[1];
    const float*  W_lins = (const float*)d_in[2];
    const float*  b_lins = (const float*)d_in[3];
    const float*  W1     = (const float*)d_in[4];
    const float*  b1     = (const float*)d_in[5];
    const float*  W2     = (const float*)d_in[6];
    const float*  b2     = (const float*)d_in[7];
    const float*  Wm1    = (const float*)d_in[8];
    const float*  bm1    = (const float*)d_in[9];
    const float*  Wm2    = (const float*)d_in[10];
    const float*  bm2    = (const float*)d_in[11];
    float* out = (float*)d_out;

    static int nsm = 0;
    if (nsm == 0) {
        cudaDeviceGetAttribute(&nsm, cudaDevAttrMultiProcessorCount, 0);
        if (nsm <= 0) nsm = 148;
        cudaFuncSetAttribute(k_node, cudaFuncAttributeMaxDynamicSharedMemorySize, SMEM_K1);
    }

    k_node<<<nsm, 512, SMEM_K1>>>(emb4, batch, W_lins, b_lins, W1, b1, W2, b2);
    k_agg<<<B_SEG / 4, 128>>>(Wm1, bm1, Wm2, bm2, out);
}

// round 13
// speedup vs baseline: 1.6226x; 1.1317x over previous
#include <cuda_runtime.h>
#include <cuda_fp16.h>
#include <float.h>
#include <math.h>
#include <cstdint>

#define N_NODES 131072
#define B_SEG   1024
#define H_DIM   128
#define TILE_N  128
#define NTILES  (N_NODES / TILE_N)
#define NSTAGES 3

// Tiles: [128 rows][136 halves] -> 272 B row stride (16B-aligned, 17x16B units)
#define A_STRIDE 136
#define B_STRIDE 136

__device__ float g_v[N_NODES];
__device__ int   g_off[B_SEG + 1];

// ---- k_node smem layout (bytes) ----
static constexpr int STAGE   = 34816;                   // A fp16 tile per stage
static constexpr int SM_B    = NSTAGES * STAGE;         // 104448
static constexpr int SM_FLT  = SM_B + 34816;            // 139264
// floats: lins[3][128]=384, ps[2][128][4]=1024 -> 1408 floats
static constexpr int SMEM_K1 = SM_FLT + 1408 * 4;       // 144896

// ---------------------------------------------------------------------------
__device__ __forceinline__ uint32_t smem_u32(const void* p) {
    uint32_t a;
    asm("{ .reg .u64 t; cvta.to.shared.u64 t, %1; cvt.u32.u64 %0, t; }"
        : "=r"(a) : "l"(p));
    return a;
}
__device__ __forceinline__ void ldsm_x4(uint32_t* r, uint32_t a) {
    asm volatile("ldmatrix.sync.aligned.m8n8.x4.shared.b16 {%0,%1,%2,%3}, [%4];"
                 : "=r"(r[0]), "=r"(r[1]), "=r"(r[2]), "=r"(r[3]) : "r"(a));
}
__device__ __forceinline__ void ldsm_x2t(uint32_t* r, uint32_t a) {
    asm volatile("ldmatrix.sync.aligned.m8n8.x2.trans.shared.b16 {%0,%1}, [%2];"
                 : "=r"(r[0]), "=r"(r[1]) : "r"(a));
}
__device__ __forceinline__ void mma16816(float* d, const uint32_t* a, const uint32_t* b) {
    asm volatile(
        "mma.sync.aligned.m16n8k16.row.col.f32.f16.f16.f32 "
        "{%0,%1,%2,%3}, {%4,%5,%6,%7}, {%8,%9}, {%0,%1,%2,%3};"
        : "+f"(d[0]), "+f"(d[1]), "+f"(d[2]), "+f"(d[3])
        : "r"(a[0]), "r"(a[1]), "r"(a[2]), "r"(a[3]), "r"(b[0]), "r"(b[1]));
}

// ---------------------------------------------------------------------------
// Kernel 1: persistent symmetric node readout with cross-tile software pipeline
//   each iteration: interleave [prefetch tile t+1 -> stage s1] with
//   [MMA on stage s0 for tile t], one __syncthreads per tile.
// ---------------------------------------------------------------------------
__global__ __launch_bounds__(512, 1)
void k_node(const float4* __restrict__ emb4,
            const int*    __restrict__ batch,
            const float*  __restrict__ W_lins,
            const float*  __restrict__ b_lins,
            const float*  __restrict__ W1,
            const float*  __restrict__ b1,
            const float*  __restrict__ W2,
            const float*  __restrict__ b2)
{
    extern __shared__ __align__(16) char smem[];
    float* lins = (float*)(smem + SM_FLT);   // [3][128]
    float* ps   = lins + NSTAGES * 128;      // [2][128][4]

    const int tid  = threadIdx.x;
    const int lane = tid & 31;
    const int wid  = tid >> 5;
    const uint32_t sbase = smem_u32(smem);

    // ---- prelude: segment-offset scatter (batch sorted) ----
    for (int i = blockIdx.x * 512 + tid; i < N_NODES; i += gridDim.x * 512) {
        int b    = batch[i];
        int prev = (i == 0) ? -1 : batch[i - 1];
        for (int bb = prev + 1; bb <= b; ++bb) g_off[bb] = i;
        if (i == N_NODES - 1)
            for (int bb = b + 1; bb <= B_SEG; ++bb) g_off[bb] = N_NODES;
    }

    // one-time staging: W1 -> fp16 B tile
    {
        char* Bh = smem + SM_B;
        for (int i = tid; i < 128 * 128 / 4; i += 512) {
            float4 w = ((const float4*)W1)[i];
            int c  = i >> 5;
            int h4 = (i & 31) * 4;
            int off = (c * B_STRIDE + h4) * 2;
            *(__half2*)(Bh + off)     = __floats2half2_rn(w.x, w.y);
            *(__half2*)(Bh + off + 4) = __floats2half2_rn(w.z, w.w);
        }
    }

    // per-lane constants
    float wlr[3][4];
    #pragma unroll
    for (int r = 0; r < 3; ++r)
        #pragma unroll
        for (int cc = 0; cc < 4; ++cc)
            wlr[r][cc] = W_lins[r * 128 + cc * 32 + lane];

    const int wm = wid >> 2;          // MMA row group (0..3) -> rows wm*32
    const int wn = wid & 3;           // MMA col group (0..3) -> cols wn*32
    const int lr = lane & 15;
    const int lk = (lane >> 4) * 8;
    const int gid = lane >> 2;
    const int tig = lane & 3;

    float b1r[4][2], w2r[4][2];
    #pragma unroll
    for (int nt = 0; nt < 4; ++nt)
        #pragma unroll
        for (int j = 0; j < 2; ++j) {
            int col = wn * 32 + nt * 8 + tig * 2 + j;
            b1r[nt][j] = b1[col];
            w2r[nt][j] = W2[col];
        }
    const float cst = b_lins[0] + b_lins[1] + b_lins[2] + b2[0];

    const uint32_t aB = sbase + SM_B;

    // chunk helpers operate on 2 nodes (nl, nl+1), contiguous-c layout
    float4 x[2][4];

    #define LOAD_CHUNK(n0_, nl_)                                             \
        do {                                                                 \
            _Pragma("unroll")                                                \
            for (int k_ = 0; k_ < 2; ++k_) {                                 \
                const float4* p_ = emb4 + (size_t)((n0_) + (nl_) + k_) * 128 + lane; \
                x[k_][0] = p_[0];                                            \
                x[k_][1] = p_[32];                                           \
                x[k_][2] = p_[64];                                           \
                x[k_][3] = p_[96];                                           \
            }                                                                \
        } while (0)

    #define CONV_CHUNK(AhS_, linsS_, nl_)                                    \
        do {                                                                 \
            _Pragma("unroll")                                                \
            for (int k_ = 0; k_ < 2; ++k_) {                                 \
                float l_ = 0.f;                                              \
                _Pragma("unroll")                                            \
                for (int cc_ = 0; cc_ < 4; ++cc_) {                          \
                    int c_ = cc_ * 32 + lane;                                \
                    l_ = fmaf(x[k_][cc_].x, wlr[0][cc_], l_);                \
                    l_ = fmaf(x[k_][cc_].y, wlr[1][cc_], l_);                \
                    l_ = fmaf(x[k_][cc_].z, wlr[2][cc_], l_);                \
                    *(__half*)((AhS_) + (((nl_) + k_) * A_STRIDE + c_) * 2) = \
                        __float2half_rn(x[k_][cc_].w);                       \
                }                                                            \
                _Pragma("unroll")                                            \
                for (int d_ = 16; d_ > 0; d_ >>= 1)                          \
                    l_ += __shfl_xor_sync(0xffffffffu, l_, d_);              \
                if (lane == 0) (linsS_)[(nl_) + k_] = l_;                    \
            }                                                                \
        } while (0)

    #define MMA_K2(aA_, k0base_)                                             \
        do {                                                                 \
            _Pragma("unroll")                                                \
            for (int kk_ = 0; kk_ < 2; ++kk_) {                              \
                int k0_ = (k0base_) + kk_ * 16;                              \
                uint32_t bh_[4][2];                                          \
                _Pragma("unroll")                                            \
                for (int nt_ = 0; nt_ < 4; ++nt_) {                          \
                    uint32_t boff_ = (uint32_t)(((k0_ + lr) * B_STRIDE + wn * 32 + nt_ * 8) * 2); \
                    ldsm_x2t(bh_[nt_], aB + boff_);                          \
                }                                                            \
                _Pragma("unroll")                                            \
                for (int mt_ = 0; mt_ < 2; ++mt_) {                          \
                    uint32_t aoff_ = (uint32_t)(((wm * 32 + mt_ * 16 + lr) * A_STRIDE + k0_ + lk) * 2); \
                    uint32_t ah_[4];                                         \
                    ldsm_x4(ah_, (aA_) + aoff_);                             \
                    _Pragma("unroll")                                        \
                    for (int nt_ = 0; nt_ < 4; ++nt_)                        \
                        mma16816(acc[mt_][nt_], ah_, bh_[nt_]);              \
                }                                                            \
            }                                                                \
        } while (0)

    __syncthreads();

    // ---- prologue: load tile t0 into stage 0 ----
    int t = blockIdx.x;
    if (t < NTILES) {
        char*  Ah0   = smem;
        float* lins0 = lins;
        const int n0p = t * TILE_N;
        #pragma unroll 1
        for (int ch = 0; ch < 4; ++ch) {
            int nl = wid * 8 + ch * 2;
            LOAD_CHUNK(n0p, nl);
            CONV_CHUNK(Ah0, lins0, nl);
        }
    }
    __syncthreads();

    int it = 0;
    for (; t < NTILES; t += gridDim.x, ++it) {
        const int s0 = it % NSTAGES;
        const int s1 = (it + 1) % NSTAGES;
        const int n0 = t * TILE_N;
        const int tn = t + gridDim.x;
        const bool has_next = (tn < NTILES);
        const int n0n = tn * TILE_N;

        char*  AhN   = smem + s1 * STAGE;
        float* linsN = lins + s1 * 128;
        const uint32_t aA = sbase + s0 * STAGE;
        const int nb = wid * 8;

        float acc[2][4][4];
        #pragma unroll
        for (int mt = 0; mt < 2; ++mt)
            #pragma unroll
            for (int nt = 0; nt < 4; ++nt)
                #pragma unroll
                for (int r = 0; r < 4; ++r) acc[mt][nt][r] = 0.f;

        // interleaved: prefetch chunks of tile t+1 while MMA'ing tile t
        if (has_next) LOAD_CHUNK(n0n, nb + 0);
        MMA_K2(aA, 0);
        if (has_next) { CONV_CHUNK(AhN, linsN, nb + 0); LOAD_CHUNK(n0n, nb + 2); }
        MMA_K2(aA, 32);
        if (has_next) { CONV_CHUNK(AhN, linsN, nb + 2); LOAD_CHUNK(n0n, nb + 4); }
        MMA_K2(aA, 64);
        if (has_next) { CONV_CHUNK(AhN, linsN, nb + 4); LOAD_CHUNK(n0n, nb + 6); }
        MMA_K2(aA, 96);
        if (has_next) CONV_CHUNK(AhN, linsN, nb + 6);

        // epilogue: relu + W2 contraction inside fragments
        float rp[2][2];
        rp[0][0] = rp[0][1] = rp[1][0] = rp[1][1] = 0.f;
        #pragma unroll
        for (int mt = 0; mt < 2; ++mt)
            #pragma unroll
            for (int nt = 0; nt < 4; ++nt)
                #pragma unroll
                for (int r = 0; r < 4; ++r) {
                    float hv = acc[mt][nt][r] + b1r[nt][r & 1];
                    rp[mt][r >> 1] = fmaf(fmaxf(hv, 0.f), w2r[nt][r & 1], rp[mt][r >> 1]);
                }
        float* psI = ps + (it & 1) * 512;
        #pragma unroll
        for (int mt = 0; mt < 2; ++mt)
            #pragma unroll
            for (int h = 0; h < 2; ++h) {
                float sum = rp[mt][h];
                sum += __shfl_xor_sync(0xffffffffu, sum, 1);
                sum += __shfl_xor_sync(0xffffffffu, sum, 2);
                if (tig == 0)
                    psI[(wm * 32 + mt * 16 + gid + h * 8) * 4 + wn] = sum;
            }
        __syncthreads();                     // stage s1 full, psI ready

        if (tid < 128) {
            const float* linsS0 = lins + s0 * 128;
            g_v[n0 + tid] = linsS0[tid] + psI[tid * 4] + psI[tid * 4 + 1]
                          + psI[tid * 4 + 2] + psI[tid * 4 + 3] + cst;
        }
    }

    #undef LOAD_CHUNK
    #undef CONV_CHUNK
    #undef MMA_K2
}

// ---------------------------------------------------------------------------
// Kernel 2: warp-per-segment aggregation; offsets precomputed in k_node
// ---------------------------------------------------------------------------
#define CAP 1024

__global__ __launch_bounds__(128)
void k_agg(const float* __restrict__ Wm1,
           const float* __restrict__ bm1,
           const float* __restrict__ Wm2,
           const float* __restrict__ bm2,
           float* __restrict__ out)
{
    __shared__ float ssort[4][256];
    __shared__ float sv[CAP];
    __shared__ float red[128];
    __shared__ float aggd[12];
    __shared__ int   dlist[4];
    __shared__ int   dcount;

    const int tid  = threadIdx.x;
    const int lane = tid & 31;
    const int wid  = tid >> 5;
    const int seg  = blockIdx.x * 4 + wid;

    if (tid == 0) dcount = 0;

    // hoist MLP weights into registers (overlaps the g_off->g_v->sort chain)
    float wm1r[12][4], bm1r[4], wm2r[4];
    #pragma unroll
    for (int hh = 0; hh < 4; ++hh) {
        int h = hh * 32 + lane;
        bm1r[hh] = bm1[h];
        wm2r[hh] = Wm2[h];
        #pragma unroll
        for (int i = 0; i < 12; ++i)
            wm1r[i][hh] = Wm1[i * H_DIM + h];
    }
    __syncthreads();

    const int start = g_off[seg];
    const int cnt   = g_off[seg + 1] - start;

    if (cnt > 256) {
        if (lane == 0) { int p = atomicAdd(&dcount, 1); dlist[p] = wid; }
    } else {
        float v[8];
        float sum = 0.f;
        #pragma unroll
        for (int r = 0; r < 8; ++r) {
            int i = r * 32 + lane;
            float x = (i < cnt) ? g_v[start + i] : FLT_MAX;
            v[r] = x;
            if (i < cnt) sum += x;
        }
        #pragma unroll
        for (int d = 16; d > 0; d >>= 1) sum += __shfl_xor_sync(0xffffffffu, sum, d);

        // fixed 256-element bitonic network: idx = r*32 + lane
        #pragma unroll
        for (int k = 2; k <= 256; k <<= 1) {
            #pragma unroll
            for (int j = k >> 1; j > 0; j >>= 1) {
                if (j >= 32) {
                    const int jr = j >> 5;
                    #pragma unroll
                    for (int r = 0; r < 8; ++r) {
                        if ((r & jr) == 0) {
                            int rp = r | jr;
                            bool up = (((r * 32) & k) == 0);
                            float a = v[r], b = v[rp];
                            float lo = fminf(a, b), hi = fmaxf(a, b);
                            v[r]  = up ? lo : hi;
                            v[rp] = up ? hi : lo;
                        }
                    }
                } else {
                    #pragma unroll
                    for (int r = 0; r < 8; ++r) {
                        float other = __shfl_xor_sync(0xffffffffu, v[r], j);
                        bool lower = (lane & j) == 0;
                        bool up = (k < 32) ? ((lane & k) == 0) : (((r * 32) & k) == 0);
                        v[r] = (up == lower) ? fminf(v[r], other) : fmaxf(v[r], other);
                    }
                }
            }
        }

        #pragma unroll
        for (int r = 0; r < 8; ++r) ssort[wid][r * 32 + lane] = v[r];
        __syncwarp();

        float agg[12];
        if (cnt > 0) {
            const float* sw = ssort[wid];
            agg[0] = sum / (float)cnt;
            agg[1] = sw[cnt - 1];
            agg[2] = sw[0];
            #pragma unroll
            for (int qi = 0; qi < 9; ++qi) {
                float q    = (float)(qi + 1) * 0.1f;
                float pos  = q * (float)(cnt - 1);
                float f    = floorf(pos);
                float frac = pos - f;
                int lo = (int)f;
                if (lo > cnt - 1) lo = cnt - 1;
                if (lo < 0) lo = 0;
                int hi = lo + 1;
                if (hi > cnt - 1) hi = cnt - 1;
                agg[3 + qi] = sw[lo] + frac * (sw[hi] - sw[lo]);
            }
        } else {
            #pragma unroll
            for (int i = 0; i < 12; ++i) agg[i] = 0.f;
        }

        // MLP in-warp (weights already in registers)
        float c = 0.f;
        #pragma unroll
        for (int hh = 0; hh < 4; ++hh) {
            float hj = bm1r[hh];
            #pragma unroll
            for (int i = 0; i < 12; ++i)
                hj = fmaf(agg[i], wm1r[i][hh], hj);
            c = fmaf(fmaxf(hj, 0.f), wm2r[hh], c);
        }
        #pragma unroll
        for (int d = 16; d > 0; d >>= 1) c += __shfl_xor_sync(0xffffffffu, c, d);
        if (lane == 0) out[seg] = c + bm2[0];
    }
    __syncthreads();

    // ---- deferred (cnt > 256) segments: block-wide bitonic path ----
    for (int d = 0; d < dcount; ++d) {
        const int dseg   = blockIdx.x * 4 + dlist[d];
        const int dstart = g_off[dseg];
        const int dcnt   = g_off[dseg + 1] - dstart;

        int m = 1;
        while (m < dcnt) m <<= 1;
        if (m > CAP) m = CAP;

        for (int i = tid; i < m; i += 128)
            sv[i] = (i < dcnt && i < CAP) ? g_v[dstart + i] : FLT_MAX;
        __syncthreads();

        for (int ksz = 2; ksz <= m; ksz <<= 1) {
            for (int j = ksz >> 1; j > 0; j >>= 1) {
                for (int i = tid; i < m; i += 128) {
                    int p = i ^ j;
                    if (p > i) {
                        bool up = ((i & ksz) == 0);
                        float x = sv[i], y = sv[p];
                        if (up ? (x > y) : (x < y)) { sv[i] = y; sv[p] = x; }
                    }
                }
                __syncthreads();
            }
        }

        float ls = 0.f;
        for (int i = tid; i < dcnt; i += 128) ls += sv[i];
        red[tid] = ls;
        __syncthreads();
        for (int s = 64; s > 0; s >>= 1) {
            if (tid < s) red[tid] += red[tid + s];
            __syncthreads();
        }
        if (tid == 0) aggd[0] = red[0] / (float)dcnt;
        if (tid == 1) aggd[1] = sv[dcnt - 1];
        if (tid == 2) aggd[2] = sv[0];
        if (tid < 9) {
            float q    = (float)(tid + 1) * 0.1f;
            float pos  = q * (float)(dcnt - 1);
            float f    = floorf(pos);
            float frac = pos - f;
            int lo = (int)f;
            if (lo > dcnt - 1) lo = dcnt - 1;
            if (lo < 0) lo = 0;
            int hi = lo + 1;
            if (hi > dcnt - 1) hi = dcnt - 1;
            aggd[3 + tid] = sv[lo] + frac * (sv[hi] - sv[lo]);
        }
        __syncthreads();

        float contrib = 0.f;
        if (tid < H_DIM) {
            float hj = bm1[tid];
            #pragma unroll
            for (int i = 0; i < 12; ++i)
                hj = fmaf(aggd[i], Wm1[i * H_DIM + tid], hj);
            hj = fmaxf(hj, 0.f);
            contrib = hj * Wm2[tid];
        }
        red[tid] = contrib;
        __syncthreads();
        for (int s = 64; s > 0; s >>= 1) {
            if (tid < s) red[tid] += red[tid + s];
            __syncthreads();
        }
        if (tid == 0) out[dseg] = red[0] + bm2[0];
        __syncthreads();
    }
}

// ---------------------------------------------------------------------------
extern "C" void kernel_launch(void* const* d_in, const int* in_sizes, int n_in,
                              void* d_out, int out_size)
{
    const float4* emb4   = (const float4*)d_in[0];
    const int*    batch  = (const int*)  d_in[1];
    const float*  W_lins = (const float*)d_in[2];
    const float*  b_lins = (const float*)d_in[3];
    const float*  W1     = (const float*)d_in[4];
    const float*  b1     = (const float*)d_in[5];
    const float*  W2     = (const float*)d_in[6];
    const float*  b2     = (const float*)d_in[7];
    const float*  Wm1    = (const float*)d_in[8];
    const float*  bm1    = (const float*)d_in[9];
    const float*  Wm2    = (const float*)d_in[10];
    const float*  bm2    = (const float*)d_in[11];
    float* out = (float*)d_out;

    static int nsm = 0;
    if (nsm == 0) {
        cudaDeviceGetAttribute(&nsm, cudaDevAttrMultiProcessorCount, 0);
        if (nsm <= 0) nsm = 148;
        cudaFuncSetAttribute(k_node, cudaFuncAttributeMaxDynamicSharedMemorySize, SMEM_K1);
    }

    k_node<<<nsm, 512, SMEM_K1>>>(emb4, batch, W_lins, b_lins, W1, b1, W2, b2);
    k_agg<<<B_SEG / 4, 128>>>(Wm1, bm1, Wm2, bm2, out);
}